// round 1
// baseline (speedup 1.0000x reference)
#include <cuda_runtime.h>

#define NN   100000
#define NE   1600000
#define INF_ 128
#define OUTF 64

// Scratch (no cudaMalloc allowed): 2 x 25.6 MB
__device__ float g_support[(size_t)NN * OUTF];
__device__ float g_resid[(size_t)NN * OUTF];

// ---------------------------------------------------------------------------
// Kernel 1: fused dual GEMM.
//   g_support[n, f] = sum_k x[n,k] * weight[k,f]            (f in 0..63)
//   g_resid  [n, o] = sum_k x[n,k] * res_w[o,k] + res_b[o]  (o in 0..63)
// Combined weight tile Wc[128 k][128 f]: f<64 -> weight, f>=64 -> res_w^T.
// Block: 256 threads = 32 (feature groups of 4) x 8 (node groups of 8).
// Tile: 64 nodes/block. K chunked by 32 through SMEM.
// ---------------------------------------------------------------------------
#define TILE_M 64
#define KC     32
#define XSS    36   // KC + 4 pad (keeps float4 alignment, breaks bank repeats)
#define GEMM_SMEM ((128 * 128 + TILE_M * XSS) * 4)

__global__ void __launch_bounds__(256) gemm_kernel(
    const float* __restrict__ x, const float* __restrict__ weight,
    const float* __restrict__ res_w, const float* __restrict__ res_b) {
  extern __shared__ float smem[];
  float* Wc = smem;               // [128][128]
  float* xs = smem + 128 * 128;   // [TILE_M][XSS]
  const int tid = threadIdx.x;
  const int tx = tid & 31;        // feature group: features tx*4 .. tx*4+3 (of 128)
  const int ty = tid >> 5;        // node group: nodes ty*8 .. ty*8+7
  const int n0 = blockIdx.x * TILE_M;

  // Load combined weights into SMEM (one-time per block)
  for (int i = tid; i < 128 * 64; i += 256) {
    int k = i >> 6, f = i & 63;
    Wc[k * 128 + f] = weight[i];              // weight is [128,64] row-major
  }
  for (int i = tid; i < 64 * 128; i += 256) {
    int o = i >> 7, k = i & 127;
    Wc[k * 128 + 64 + o] = res_w[i];          // res_w is [64,128] row-major
  }

  float acc[8][4];
#pragma unroll
  for (int i = 0; i < 8; i++)
#pragma unroll
    for (int j = 0; j < 4; j++) acc[i][j] = 0.f;

  for (int k0 = 0; k0 < INF_; k0 += KC) {
    __syncthreads();
    // Stage x chunk: 64 nodes x 32 k, float4 coalesced loads
    for (int i = tid; i < TILE_M * (KC / 4); i += 256) {
      int node = i >> 3;   // KC/4 == 8
      int kq = i & 7;
      int gn = n0 + node;
      float4 v = make_float4(0.f, 0.f, 0.f, 0.f);
      if (gn < NN) v = *(const float4*)(x + (size_t)gn * INF_ + k0 + kq * 4);
      *(float4*)(xs + node * XSS + kq * 4) = v;
    }
    __syncthreads();

    const float* Wk = Wc + k0 * 128 + tx * 4;
    const float* xrow = xs + (ty * 8) * XSS;
#pragma unroll
    for (int kk = 0; kk < KC; kk++) {
      float4 wv = *(const float4*)(Wk + kk * 128);
#pragma unroll
      for (int i = 0; i < 8; i++) {
        float xv = xrow[i * XSS + kk];
        acc[i][0] = fmaf(xv, wv.x, acc[i][0]);
        acc[i][1] = fmaf(xv, wv.y, acc[i][1]);
        acc[i][2] = fmaf(xv, wv.z, acc[i][2]);
        acc[i][3] = fmaf(xv, wv.w, acc[i][3]);
      }
    }
  }

  // Epilogue: tx<16 -> support features, tx>=16 -> residual features (+res_b)
  if (tx < 16) {
    const int f = tx * 4;
#pragma unroll
    for (int i = 0; i < 8; i++) {
      int gn = n0 + ty * 8 + i;
      if (gn < NN) {
        float4 v = make_float4(acc[i][0], acc[i][1], acc[i][2], acc[i][3]);
        *(float4*)(g_support + (size_t)gn * OUTF + f) = v;
      }
    }
  } else {
    const int f = (tx - 16) * 4;
    float4 rb = *(const float4*)(res_b + f);
#pragma unroll
    for (int i = 0; i < 8; i++) {
      int gn = n0 + ty * 8 + i;
      if (gn < NN) {
        float4 v = make_float4(acc[i][0] + rb.x, acc[i][1] + rb.y,
                               acc[i][2] + rb.z, acc[i][3] + rb.w);
        *(float4*)(g_resid + (size_t)gn * OUTF + f) = v;
      }
    }
  }
}

// ---------------------------------------------------------------------------
// Kernel 2: edge scatter. 16 threads per edge, each moves one float4 (16B).
// out[dst, :] += w_e * support[src, :] via red.global.add.v4.f32 (L2 atomics).
// support + out both L2-resident (25.6 MB each vs 126 MB L2).
// ---------------------------------------------------------------------------
__global__ void __launch_bounds__(256) scatter_kernel(
    const int* __restrict__ src, const int* __restrict__ dst,
    const float* __restrict__ ew, float* __restrict__ out) {
  long long t = (long long)blockIdx.x * blockDim.x + threadIdx.x;
  int e = (int)(t >> 4);
  int q = (int)(t & 15);
  if (e >= NE) return;
  int s = __ldg(src + e);
  int d = __ldg(dst + e);
  float w = __ldg(ew + e);
  float4 v = __ldg((const float4*)(g_support + (size_t)s * OUTF) + q);
  v.x *= w; v.y *= w; v.z *= w; v.w *= w;
  float* p = out + (size_t)d * OUTF + q * 4;
  asm volatile("red.global.add.v4.f32 [%0], {%1, %2, %3, %4};"
               :: "l"(p), "f"(v.x), "f"(v.y), "f"(v.z), "f"(v.w)
               : "memory");
}

// ---------------------------------------------------------------------------
// Kernel 3: finalize. 16 lanes per node: +bias, LayerNorm(64), ReLU, +resid.
// ---------------------------------------------------------------------------
__global__ void __launch_bounds__(256) finalize_kernel(
    float* __restrict__ out, const float* __restrict__ bias,
    const float* __restrict__ gamma, const float* __restrict__ beta) {
  long long t = (long long)blockIdx.x * blockDim.x + threadIdx.x;
  int n = (int)(t >> 4);
  int q = (int)(t & 15);
  if (n >= NN) return;

  float4 v = *(float4*)(out + (size_t)n * OUTF + q * 4);
  float4 b = *(const float4*)(bias + q * 4);
  v.x += b.x; v.y += b.y; v.z += b.z; v.w += b.w;

  float s  = v.x + v.y + v.z + v.w;
  float s2 = v.x * v.x + v.y * v.y + v.z * v.z + v.w * v.w;
#pragma unroll
  for (int m = 8; m >= 1; m >>= 1) {
    s  += __shfl_xor_sync(0xffffffffu, s, m);
    s2 += __shfl_xor_sync(0xffffffffu, s2, m);
  }
  float mu  = s * (1.f / 64.f);
  float var = s2 * (1.f / 64.f) - mu * mu;
  float inv = rsqrtf(var + 1e-5f);

  float4 g  = *(const float4*)(gamma + q * 4);
  float4 be = *(const float4*)(beta + q * 4);
  float4 r  = *(const float4*)(g_resid + (size_t)n * OUTF + q * 4);

  v.x = fmaxf((v.x - mu) * inv * g.x + be.x, 0.f) + r.x;
  v.y = fmaxf((v.y - mu) * inv * g.y + be.y, 0.f) + r.y;
  v.z = fmaxf((v.z - mu) * inv * g.z + be.z, 0.f) + r.z;
  v.w = fmaxf((v.w - mu) * inv * g.w + be.w, 0.f) + r.w;

  *(float4*)(out + (size_t)n * OUTF + q * 4) = v;
}

// ---------------------------------------------------------------------------
extern "C" void kernel_launch(void* const* d_in, const int* in_sizes, int n_in,
                              void* d_out, int out_size) {
  const float* x      = (const float*)d_in[0];
  const float* weight = (const float*)d_in[1];
  const float* bias   = (const float*)d_in[2];
  const float* gamma  = (const float*)d_in[3];
  const float* beta   = (const float*)d_in[4];
  const float* res_w  = (const float*)d_in[5];
  const float* res_b  = (const float*)d_in[6];
  const float* ew     = (const float*)d_in[7];
  const int*   esrc   = (const int*)d_in[8];
  const int*   edst   = (const int*)d_in[9];
  float* out = (float*)d_out;

  cudaFuncSetAttribute(gemm_kernel,
                       cudaFuncAttributeMaxDynamicSharedMemorySize, GEMM_SMEM);

  // Zero the accumulator (d_out is poisoned to 0xAA before timing)
  cudaMemsetAsync(d_out, 0, (size_t)NN * OUTF * sizeof(float), 0);

  gemm_kernel<<<(NN + TILE_M - 1) / TILE_M, 256, GEMM_SMEM>>>(x, weight, res_w, res_b);

  long long sthreads = (long long)NE * 16;
  scatter_kernel<<<(unsigned)((sthreads + 255) / 256), 256>>>(esrc, edst, ew, out);

  long long fthreads = (long long)NN * 16;
  finalize_kernel<<<(unsigned)((fthreads + 255) / 256), 256>>>(out, bias, gamma, beta);
}